// round 15
// baseline (speedup 1.0000x reference)
#include <cuda_runtime.h>
#include <cuda_fp16.h>
#include <math.h>
#include <stdint.h>

#define D_MODEL 1024
#define NHEADS 16
#define DHEAD 64
#define BATCH 4
#define SEQL 4096
#define MROWS (BATCH*SEQL)      /* 16384 */
#define DFF (4*D_MODEL)         /* 4096  */
#define QKVG_N (4*D_MODEL)      /* 4096  */
#define EPSLN 1e-5f
#define NCHUNK 16
#define CLEN (SEQL/NCHUNK)      /* 256   */

// ---------------- scratch (device globals; no allocation allowed) ----------
__device__ __half g_qkvg[(size_t)MROWS*QKVG_N];  // cols: [q | k | v | g]
__device__ float  g_x2  [MROWS*D_MODEL];
__device__ __half g_y   [MROWS*D_MODEL];
__device__ __half g_attn[MROWS*D_MODEL];
__device__ __half g_h   [MROWS*D_MODEL];
__device__ __half g_ff1 [(size_t)MROWS*DFF];
__device__ float  g_P   [BATCH*NHEADS*NCHUNK*DHEAD];
__device__ float  g_bqkvg[QKVG_N];
// transposed fp16 weights [N,K]
__device__ __half g_wtqkvg[(size_t)QKVG_N*D_MODEL];
__device__ __half g_wto [D_MODEL*D_MODEL];
__device__ __half g_wt1 [(size_t)D_MODEL*DFF];
__device__ __half g_wt2 [(size_t)DFF*D_MODEL];

#define CP16(dst, src) asm volatile( \
    "cp.async.cg.shared.global [%0], [%1], 16;\n" :: "r"(dst), "l"(src))
#define CPCOMMIT() asm volatile("cp.async.commit_group;\n" ::: "memory")
#define CPWAIT0()  asm volatile("cp.async.wait_group 0;\n" ::: "memory")
#define LDSM4(r0, r1, r2, r3, addr) asm volatile( \
    "ldmatrix.sync.aligned.m8n8.x4.shared.b16 {%0,%1,%2,%3}, [%4];" \
    : "=r"(r0), "=r"(r1), "=r"(r2), "=r"(r3) : "r"(addr))
#define MMA16816(a0,a1,a2,a3, b0,b1, c0,c1,c2,c3) asm volatile( \
    "mma.sync.aligned.m16n8k16.row.col.f32.f16.f16.f32 " \
    "{%0,%1,%2,%3}, {%4,%5,%6,%7}, {%8,%9}, {%0,%1,%2,%3};\n" \
    : "+f"(c0), "+f"(c1), "+f"(c2), "+f"(c3) \
    : "r"(a0), "r"(a1), "r"(a2), "r"(a3), "r"(b0), "r"(b1))

// bank-swizzle value for a row (16B units): v(r) = ((r>>1)&3) ^ ((r>>3)&1)
__device__ __forceinline__ uint32_t swz(int r) {
    return (uint32_t)((((r >> 1) & 3) ^ ((r >> 3) & 1)) * 16);
}

// ---------------- all weight transposes in ONE launch -----------------------
__global__ void transpose_all(const float* __restrict__ Wq, const float* __restrict__ Wk,
                              const float* __restrict__ Wv, const float* __restrict__ Wg,
                              const float* __restrict__ Wo, const float* __restrict__ W1,
                              const float* __restrict__ W2) {
    __shared__ float t[32][33];
    int id = blockIdx.x;
    const float* W; __half* Wt; int K, N, bx, by;
    __half *wtqkvg = g_wtqkvg, *wto = g_wto, *wt1 = g_wt1, *wt2 = g_wt2;
    if (id < 4096) {
        int seg = id >> 10, r = id & 1023;
        const float* srcs[4] = {Wq, Wk, Wv, Wg};
        W = srcs[seg];
        Wt = wtqkvg + (size_t)seg * D_MODEL * D_MODEL;
        K = D_MODEL; N = D_MODEL; bx = r & 31; by = r >> 5;
    } else if (id < 5120) {
        int r = id - 4096;
        W = Wo; Wt = wto; K = D_MODEL; N = D_MODEL; bx = r & 31; by = r >> 5;
    } else if (id < 9216) {
        int r = id - 5120;
        W = W1; Wt = wt1; K = D_MODEL; N = DFF; bx = r & 127; by = r >> 7;
    } else {
        int r = id - 9216;
        W = W2; Wt = wt2; K = DFF; N = D_MODEL; bx = r & 31; by = r >> 5;
    }
    int n0 = bx * 32, k0 = by * 32;
    int tx = threadIdx.x, ty = threadIdx.y;
    t[ty][tx] = W[(size_t)(k0 + ty) * N + n0 + tx];
    __syncthreads();
    Wt[(size_t)(n0 + ty) * K + k0 + tx] = __float2half_rn(t[tx][ty]);
}

__global__ void pack_bias(const float* __restrict__ bq, const float* __restrict__ bk,
                          const float* __restrict__ bv, const float* __restrict__ bg,
                          float* __restrict__ o) {
    int i = blockIdx.x * 256 + threadIdx.x;
    float r;
    if      (i < 1024) r = bq[i];
    else if (i < 2048) r = bk[i - 1024];
    else if (i < 3072) r = bv[i - 2048];
    else               r = bg[i - 3072];
    o[i] = r;
}

// ---------------- LayerNorm: one block per row, out = fp16 ------------------
__global__ void ln_kernel(const float* __restrict__ x,
                          const float* __restrict__ gw,
                          const float* __restrict__ bw,
                          __half* __restrict__ out) {
    int row = blockIdx.x;
    int t = threadIdx.x;
    const float4* xr = (const float4*)(x + (size_t)row * D_MODEL);
    float4 v = xr[t];
    float s  = v.x + v.y + v.z + v.w;
    float ss = v.x*v.x + v.y*v.y + v.z*v.z + v.w*v.w;
    #pragma unroll
    for (int o = 16; o > 0; o >>= 1) {
        s  += __shfl_xor_sync(0xFFFFFFFFu, s,  o);
        ss += __shfl_xor_sync(0xFFFFFFFFu, ss, o);
    }
    __shared__ float red[2][8];
    int warp = t >> 5, lane = t & 31;
    if (lane == 0) { red[0][warp] = s; red[1][warp] = ss; }
    __syncthreads();
    if (t == 0) {
        float a = 0.f, c = 0.f;
        #pragma unroll
        for (int i = 0; i < 8; i++) { a += red[0][i]; c += red[1][i]; }
        float mu  = a * (1.f / D_MODEL);
        float var = c * (1.f / D_MODEL) - mu * mu;
        red[0][0] = mu;
        red[1][0] = rsqrtf(var + EPSLN);
    }
    __syncthreads();
    float mu = red[0][0], rs = red[1][0];
    float4 gv = ((const float4*)gw)[t];
    float4 bv = ((const float4*)bw)[t];
    __half2 h0 = __floats2half2_rn((v.x - mu) * rs * gv.x + bv.x,
                                   (v.y - mu) * rs * gv.y + bv.y);
    __half2 h1 = __floats2half2_rn((v.z - mu) * rs * gv.z + bv.z,
                                   (v.w - mu) * rs * gv.w + bv.w);
    __half2* op = (__half2*)(out + (size_t)row * D_MODEL + t * 4);
    op[0] = h0;
    op[1] = h1;
}

// ---------------- FP16 tensor-core GEMM -------------------------------------
// 128x128 block tile, BK=32, 256 threads (8 warps 2x4), warp tile 64x32,
// mma.sync.m16n8k16.f16 fp32-acc, xor-swizzled conflict-free ldmatrix,
// cp.async double buffer, per-warp k-step phase stagger + LDSM/MMA interleave.
// EPI: 0 bias, 1 bias+sigmoid, 2 bias+residual, 3 bias+gelu,
//      4 bias + sigmoid only for n >= 3*D_MODEL (fused QKVG epilogue)
// OUTH: 1 -> C fp16, else fp32.
template <int EPI, int OUTH>
__global__ __launch_bounds__(256, 2) void hgemm(
        const __half* __restrict__ A, const __half* __restrict__ Bt,
        const float* __restrict__ bias, const float* __restrict__ Res,
        void* __restrict__ Cv, int K, int N) {
    __shared__ __half As[2][128][32];   // 64B rows, xor-swizzled chunks
    __shared__ __half Bs[2][128][32];

    int tid  = threadIdx.x;
    int bm   = blockIdx.y * 128, bn = blockIdx.x * 128;
    int warp = tid >> 5, lane = tid & 31;
    int wm   = (warp >> 2) * 64;
    int wn   = (warp & 3) * 32;
    int gid  = lane >> 2, ctig = lane & 3;
    int lrow = lane & 15, lsel2 = (lane >> 4) * 16;   // byte offset 0/16
    uint32_t xv = swz(lrow);
    // phase stagger: warps {0..3} do k-steps (0,16); warps {4..7} do (16,0).
    // warps w and w+4 share an SMSP -> one loads while the other does MMA.
    uint32_t kfirst = ((uint32_t)(warp >> 2) & 1u) << 4;

    int l_row = tid >> 1;               // store row 0..127
    int c0    = (tid & 1) * 2;          // chunk 0 or 2
    uint32_t xvr = swz(l_row);

    float acc[4][4][4];
    #pragma unroll
    for (int i = 0; i < 4; i++)
        #pragma unroll
        for (int j = 0; j < 4; j++)
            #pragma unroll
            for (int r = 0; r < 4; r++) acc[i][j][r] = 0.f;

    const __half* Ag = A  + (size_t)(bm + l_row) * K + c0 * 8;
    const __half* Bg = Bt + (size_t)(bn + l_row) * K + c0 * 8;

    uint32_t as_base = (uint32_t)__cvta_generic_to_shared(&As[0][0][0]);
    uint32_t bs_base = (uint32_t)__cvta_generic_to_shared(&Bs[0][0][0]);

    auto load_tile = [&](int t, int buf) {
        int k0 = t * 32;
        uint32_t arow = as_base + buf * 8192 + l_row * 64;
        CP16(arow + (((uint32_t)(c0    * 16)) ^ xvr), Ag + k0);
        CP16(arow + (((uint32_t)((c0+1)* 16)) ^ xvr), Ag + k0 + 8);
        uint32_t brow = bs_base + buf * 8192 + l_row * 64;
        CP16(brow + (((uint32_t)(c0    * 16)) ^ xvr), Bg + k0);
        CP16(brow + (((uint32_t)((c0+1)* 16)) ^ xvr), Bg + k0 + 8);
        CPCOMMIT();
    };

    int T = K >> 5;
    load_tile(0, 0);

    for (int t = 0; t < T; t++) {
        int buf = t & 1;
        CPWAIT0();
        __syncthreads();
        if (t + 1 < T) load_tile(t + 1, buf ^ 1);

        uint32_t a_row = as_base + buf * 8192 + (wm + lrow) * 64;
        uint32_t b_row = bs_base + buf * 8192 + (wn + lrow) * 64;

        #pragma unroll
        for (int s = 0; s < 2; s++) {
            uint32_t ks = kfirst ^ ((uint32_t)s << 4);
            uint32_t off = ((uint32_t)lsel2 + ks * 2u) ^ xv;
            uint32_t af[4][4], bf[4][2];
            // B fragments first (needed by every MMA)
            #pragma unroll
            for (int p = 0; p < 2; p++) {
                uint32_t r0, r1, r2, r3;
                LDSM4(r0, r1, r2, r3, b_row + p * 1024 + off);
                bf[2*p    ][0] = r0; bf[2*p + 1][0] = r1;
                bf[2*p    ][1] = r2; bf[2*p + 1][1] = r3;
            }
            LDSM4(af[0][0], af[0][1], af[0][2], af[0][3], a_row + off);
            // interleave: issue A[im+1] load between MMA groups of im
            #pragma unroll
            for (int im = 0; im < 4; im++) {
                if (im < 3)
                    LDSM4(af[im+1][0], af[im+1][1], af[im+1][2], af[im+1][3],
                          a_row + (im + 1) * 1024 + off);
                #pragma unroll
                for (int jn = 0; jn < 4; jn++)
                    MMA16816(af[im][0], af[im][1], af[im][2], af[im][3],
                             bf[jn][0], bf[jn][1],
                             acc[im][jn][0], acc[im][jn][1],
                             acc[im][jn][2], acc[im][jn][3]);
            }
        }
    }

    // epilogue
    float* Cf = (float*)Cv;
    __half* Ch = (__half*)Cv;
    #pragma unroll
    for (int im = 0; im < 4; im++) {
        #pragma unroll
        for (int jn = 0; jn < 4; jn++) {
            int m = bm + wm + im * 16 + gid;
            int n = bn + wn + jn * 8 + ctig * 2;
            float2 bb = *(const float2*)(bias + n);
            float v0 = acc[im][jn][0] + bb.x;
            float v1 = acc[im][jn][1] + bb.y;
            float v2 = acc[im][jn][2] + bb.x;
            float v3 = acc[im][jn][3] + bb.y;
            if (EPI == 1 || (EPI == 4 && n >= 3 * D_MODEL)) {
                v0 = 1.f / (1.f + expf(-v0));
                v1 = 1.f / (1.f + expf(-v1));
                v2 = 1.f / (1.f + expf(-v2));
                v3 = 1.f / (1.f + expf(-v3));
            } else if (EPI == 2) {
                float2 r0 = *(const float2*)(Res + (size_t)m * N + n);
                float2 r1 = *(const float2*)(Res + (size_t)(m + 8) * N + n);
                v0 += r0.x; v1 += r0.y; v2 += r1.x; v3 += r1.y;
            } else if (EPI == 3) {
                const float c = 0.70710678118654752f;
                v0 = 0.5f * v0 * (1.f + erff(v0 * c));
                v1 = 0.5f * v1 * (1.f + erff(v1 * c));
                v2 = 0.5f * v2 * (1.f + erff(v2 * c));
                v3 = 0.5f * v3 * (1.f + erff(v3 * c));
            }
            if (OUTH) {
                *(__half2*)(Ch + (size_t)m * N + n)       = __floats2half2_rn(v0, v1);
                *(__half2*)(Ch + (size_t)(m + 8) * N + n) = __floats2half2_rn(v2, v3);
            } else {
                *(float2*)(Cf + (size_t)m * N + n)       = make_float2(v0, v1);
                *(float2*)(Cf + (size_t)(m + 8) * N + n) = make_float2(v2, v3);
            }
        }
    }
}

// ---------------- Retention scan (chunked associative scan) ---------------
__device__ __forceinline__ void unit_decompose(int tid, int bx,
                                               int& b, int& h, int& chunk, int& d) {
    d = tid & 63;
    int unit = bx * 4 + (tid >> 6);
    chunk = unit & (NCHUNK - 1);
    int bh = unit >> 4;
    h = bh & (NHEADS - 1);
    b = bh >> 4;
}

__global__ void scan_partial(const float* __restrict__ dlogit) {
    int b, h, chunk, d;
    unit_decompose(threadIdx.x, blockIdx.x, b, h, chunk, d);
    float decay = 1.f / (1.f + expf(-dlogit[h]));
    float p = 0.f;
    size_t base = ((size_t)(b * SEQL + chunk * CLEN)) * QKVG_N + h * DHEAD + d;
    const __half* kp = g_qkvg + base + D_MODEL;
    const __half* vp = g_qkvg + base + 2 * D_MODEL;
    #pragma unroll 4
    for (int i = 0; i < CLEN; i++) {
        size_t o = (size_t)i * QKVG_N;
        p = decay * p + __half2float(kp[o]) * __half2float(vp[o]);
    }
    int bh = b * NHEADS + h;
    g_P[(bh * NCHUNK + chunk) * DHEAD + d] = p;
}

__global__ void scan_final(const float* __restrict__ dlogit) {
    int b, h, chunk, d;
    unit_decompose(threadIdx.x, blockIdx.x, b, h, chunk, d);
    float decay = 1.f / (1.f + expf(-dlogit[h]));
    float dCL = powf(decay, (float)CLEN);
    int bh = b * NHEADS + h;
    float s = 0.f;
    for (int j = 0; j < chunk; j++)
        s = dCL * s + g_P[(bh * NCHUNK + j) * DHEAD + d];
    const float scale = 0.125f;   // DHEAD^-0.5
    int row0 = b * SEQL + chunk * CLEN;
    size_t base = (size_t)row0 * QKVG_N + h * DHEAD + d;
    const __half* qp = g_qkvg + base;
    const __half* kp = g_qkvg + base + D_MODEL;
    const __half* vp = g_qkvg + base + 2 * D_MODEL;
    const __half* gp = g_qkvg + base + 3 * D_MODEL;
    __half* ap = g_attn + (size_t)row0 * D_MODEL + h * DHEAD + d;
    #pragma unroll 4
    for (int i = 0; i < CLEN; i++) {
        size_t o = (size_t)i * QKVG_N;
        s = decay * s + __half2float(kp[o]) * __half2float(vp[o]);
        float r = __half2float(gp[o]) * __half2float(qp[o]) * s * scale;
        ap[(size_t)i * D_MODEL] = __float2half_rn(r);
    }
}

// ---------------- launch ---------------------------------------------------
extern "C" void kernel_launch(void* const* d_in, const int* in_sizes, int n_in,
                              void* d_out, int out_size) {
    const float* x      = (const float*)d_in[0];
    const float* ln1_g  = (const float*)d_in[1];
    const float* ln1_b  = (const float*)d_in[2];
    const float* Wq     = (const float*)d_in[3];
    const float* bq     = (const float*)d_in[4];
    const float* Wk     = (const float*)d_in[5];
    const float* bk     = (const float*)d_in[6];
    const float* Wv     = (const float*)d_in[7];
    const float* bv     = (const float*)d_in[8];
    const float* Wg     = (const float*)d_in[9];
    const float* bg     = (const float*)d_in[10];
    const float* dlogit = (const float*)d_in[11];
    const float* Wo     = (const float*)d_in[12];
    const float* bo     = (const float*)d_in[13];
    const float* ln2_g  = (const float*)d_in[14];
    const float* ln2_b  = (const float*)d_in[15];
    const float* W1     = (const float*)d_in[16];
    const float* b1     = (const float*)d_in[17];
    const float* W2     = (const float*)d_in[18];
    const float* b2     = (const float*)d_in[19];
    float* out = (float*)d_out;

    float  *x2, *bqkvg;
    __half *y, *attn, *h, *ff1, *qkvg;
    __half *wtqkvg, *wto, *wt1, *wt2;
    cudaGetSymbolAddress((void**)&qkvg,   g_qkvg);
    cudaGetSymbolAddress((void**)&x2,     g_x2);
    cudaGetSymbolAddress((void**)&y,      g_y);
    cudaGetSymbolAddress((void**)&attn,   g_attn);
    cudaGetSymbolAddress((void**)&h,      g_h);
    cudaGetSymbolAddress((void**)&ff1,    g_ff1);
    cudaGetSymbolAddress((void**)&bqkvg,  g_bqkvg);
    cudaGetSymbolAddress((void**)&wtqkvg, g_wtqkvg);
    cudaGetSymbolAddress((void**)&wto,    g_wto);
    cudaGetSymbolAddress((void**)&wt1,    g_wt1);
    cudaGetSymbolAddress((void**)&wt2,    g_wt2);

    transpose_all<<<13312, dim3(32, 32)>>>(Wq, Wk, Wv, Wg, Wo, W1, W2);
    pack_bias<<<QKVG_N/256, 256>>>(bq, bk, bv, bg, bqkvg);

    dim3 gQ(QKVG_N / 128, MROWS / 128);   // 32 x 128
    dim3 gD(D_MODEL / 128, MROWS / 128);  //  8 x 128
    dim3 gF(DFF / 128,     MROWS / 128);  // 32 x 128

    ln_kernel<<<MROWS, 256>>>(x, ln1_g, ln1_b, y);

    hgemm<4,1><<<gQ, 256>>>(y, wtqkvg, bqkvg, nullptr, qkvg, D_MODEL, QKVG_N);

    scan_partial<<<256, 256>>>(dlogit);
    scan_final  <<<256, 256>>>(dlogit);

    hgemm<2,0><<<gD, 256>>>(attn, wto, bo, x, x2, D_MODEL, D_MODEL);

    ln_kernel<<<MROWS, 256>>>(x2, ln2_g, ln2_b, h);

    hgemm<3,1><<<gF, 256>>>(h,   wt1, b1, nullptr, ff1, D_MODEL, DFF);
    hgemm<2,0><<<gD, 256>>>(ff1, wt2, b2, x2,      out, DFF,     D_MODEL);
}